// round 1
// baseline (speedup 1.0000x reference)
#include <cuda_runtime.h>

#define B_  16
#define NK_ 256
#define NQ_ 256
#define DK_ 256
#define H_  128
#define DV_ 256

// scratch for projections (allocation-free rule: device globals)
__device__ float g_kproj[B_ * NK_ * H_];   // (B, NK, H)
__device__ float g_qproj[B_ * NQ_ * H_];   // (B, NQ, H)

// ---------------------------------------------------------------------------
// Kernel A: projections. blockIdx.y==0 -> key@Wk, ==1 -> query@Wq.
// One block (128 threads) per output row; thread t owns output column t.
// ---------------------------------------------------------------------------
__global__ void proj_kernel(const float* __restrict__ key,
                            const float* __restrict__ query,
                            const float* __restrict__ Wk,
                            const float* __restrict__ Wq) {
    __shared__ float row[DK_];
    const float* in = blockIdx.y ? query : key;
    const float* W  = blockIdx.y ? Wq    : Wk;
    float* out      = blockIdx.y ? g_qproj : g_kproj;

    const int r = blockIdx.x;          // row in [0, B*NK)
    const int t = threadIdx.x;         // 0..127

    row[t]        = in[r * DK_ + t];
    row[t + 128]  = in[r * DK_ + t + 128];
    __syncthreads();

    float acc = 0.f;
    #pragma unroll 8
    for (int d = 0; d < DK_; ++d)
        acc = fmaf(row[d], W[d * H_ + t], acc);   // W reads coalesced over t

    out[r * H_ + t] = acc;
}

// ---------------------------------------------------------------------------
// Kernel B: scores + masked softmax + attn@value.
// One block per (b, k): 256 threads. Phase 1: thread q computes score over h.
// Phase 2: block softmax with valid_lens mask. Phase 3: thread d accumulates
// output over q (coalesced value reads).
// ---------------------------------------------------------------------------
__global__ __launch_bounds__(256)
void attn_kernel(const float* __restrict__ value,
                 const int*   __restrict__ valid_lens,
                 const float* __restrict__ wv,
                 float*       __restrict__ out) {
    const int bk = blockIdx.x;       // 0 .. B*NK-1
    const int b  = bk >> 8;          // NK = 256
    const int t  = threadIdx.x;      // 0..255
    const int lane = t & 31;
    const int wid  = t >> 5;

    __shared__ float kv[H_];
    __shared__ float wvs[H_];
    __shared__ float attn[NQ_];
    __shared__ float red[8];

    if (t < H_) {
        kv[t]  = g_kproj[bk * H_ + t];
        wvs[t] = wv[t];
    }
    __syncthreads();

    // ---- Phase 1: score for q = t ----
    const float* qrow = &g_qproj[(b * NQ_ + t) * H_];
    float s = 0.f;
    #pragma unroll 8
    for (int h = 0; h < H_; h += 4) {
        float4 qv = *reinterpret_cast<const float4*>(qrow + h);
        s = fmaf(wvs[h + 0], tanhf(kv[h + 0] + qv.x), s);
        s = fmaf(wvs[h + 1], tanhf(kv[h + 1] + qv.y), s);
        s = fmaf(wvs[h + 2], tanhf(kv[h + 2] + qv.z), s);
        s = fmaf(wvs[h + 3], tanhf(kv[h + 3] + qv.w), s);
    }
    if (t >= valid_lens[b]) s = -1000000.0f;

    // ---- Phase 2: masked softmax over the 256 scores ----
    // block max
    float m = s;
    #pragma unroll
    for (int o = 16; o > 0; o >>= 1)
        m = fmaxf(m, __shfl_xor_sync(0xffffffffu, m, o));
    if (lane == 0) red[wid] = m;
    __syncthreads();
    if (wid == 0) {
        float v = red[lane & 7];
        #pragma unroll
        for (int o = 4; o > 0; o >>= 1)
            v = fmaxf(v, __shfl_xor_sync(0xffffffffu, v, o));
        if (lane == 0) red[0] = v;
    }
    __syncthreads();
    const float mx = red[0];
    __syncthreads();

    float e = expf(s - mx);          // masked entries underflow to 0
    // block sum
    float sum = e;
    #pragma unroll
    for (int o = 16; o > 0; o >>= 1)
        sum += __shfl_xor_sync(0xffffffffu, sum, o);
    if (lane == 0) red[wid] = sum;
    __syncthreads();
    if (wid == 0) {
        float v = red[lane & 7];
        #pragma unroll
        for (int o = 4; o > 0; o >>= 1)
            v += __shfl_xor_sync(0xffffffffu, v, o);
        if (lane == 0) red[0] = v;
    }
    __syncthreads();
    const float inv = 1.0f / red[0];
    attn[t] = e * inv;
    __syncthreads();

    // ---- Phase 3: out[b,k,d] = sum_q attn[q] * value[b,q,d], d = t ----
    const float* vcol = value + (size_t)b * NQ_ * DV_ + t;
    float a0 = 0.f, a1 = 0.f, a2 = 0.f, a3 = 0.f;
    #pragma unroll 4
    for (int q = 0; q < NQ_; q += 4) {
        a0 = fmaf(attn[q + 0], vcol[(q + 0) * DV_], a0);
        a1 = fmaf(attn[q + 1], vcol[(q + 1) * DV_], a1);
        a2 = fmaf(attn[q + 2], vcol[(q + 2) * DV_], a2);
        a3 = fmaf(attn[q + 3], vcol[(q + 3) * DV_], a3);
    }
    out[(size_t)bk * DV_ + t] = (a0 + a1) + (a2 + a3);
}

// ---------------------------------------------------------------------------
extern "C" void kernel_launch(void* const* d_in, const int* in_sizes, int n_in,
                              void* d_out, int out_size) {
    const float* key        = (const float*)d_in[0];
    const float* query      = (const float*)d_in[1];
    const float* value      = (const float*)d_in[2];
    const int*   valid_lens = (const int*)  d_in[3];
    const float* Wk         = (const float*)d_in[4];
    const float* Wq         = (const float*)d_in[5];
    const float* wv         = (const float*)d_in[6];
    float* out = (float*)d_out;

    dim3 gridA(B_ * NK_, 2);
    proj_kernel<<<gridA, 128>>>(key, query, Wk, Wq);
    attn_kernel<<<B_ * NK_, 256>>>(value, valid_lens, wv, out);
}

// round 2
// speedup vs baseline: 2.4602x; 2.4602x over previous
#include <cuda_runtime.h>

#define B_  16
#define NK_ 256
#define NQ_ 256
#define DK_ 256
#define H_  128
#define DV_ 256
#define KT  8     // k-rows per attn block
#define RT  8     // rows per proj block

// scratch for projections (allocation-free rule: device globals)
__device__ float g_kproj[B_ * NK_ * H_];   // (B, NK, H)
__device__ float g_qproj[B_ * NQ_ * H_];   // (B, NQ, H)

__device__ __forceinline__ float tanh_fast(float x) {
    float y;
    asm("tanh.approx.f32 %0, %1;" : "=f"(y) : "f"(x));
    return y;
}

// ---------------------------------------------------------------------------
// Kernel A: projections, RT rows per block. blockIdx.y==0 -> key@Wk, 1 -> q@Wq.
// 128 threads; thread t owns output column t for all RT rows.
// Input rows staged transposed in smem -> broadcast LDS.128 serves 4 rows.
// ---------------------------------------------------------------------------
__global__ __launch_bounds__(128)
void proj_kernel(const float* __restrict__ key,
                 const float* __restrict__ query,
                 const float* __restrict__ Wk,
                 const float* __restrict__ Wq) {
    __shared__ float rowsT[DK_ * RT];      // rowsT[d*RT + r]
    const float* in = blockIdx.y ? query : key;
    const float* W  = blockIdx.y ? Wq    : Wk;
    float* out      = blockIdx.y ? g_qproj : g_kproj;

    const int r0 = blockIdx.x * RT;
    const int t  = threadIdx.x;            // 0..127

    // stage RT input rows, transposed
    {
        const float* src = in + (size_t)r0 * DK_;
        // 2048 elements, 128 threads, 16 each (4x float4)
        int r = t >> 4;                    // 0..7
        int d0 = (t & 15) * 16;            // 0..240
        #pragma unroll
        for (int i = 0; i < 4; ++i) {
            float4 v = *reinterpret_cast<const float4*>(src + r * DK_ + d0 + i * 4);
            rowsT[(d0 + i * 4 + 0) * RT + r] = v.x;
            rowsT[(d0 + i * 4 + 1) * RT + r] = v.y;
            rowsT[(d0 + i * 4 + 2) * RT + r] = v.z;
            rowsT[(d0 + i * 4 + 3) * RT + r] = v.w;
        }
    }
    __syncthreads();

    float acc[RT];
    #pragma unroll
    for (int r = 0; r < RT; ++r) acc[r] = 0.f;

    #pragma unroll 4
    for (int d = 0; d < DK_; ++d) {
        float w = W[d * H_ + t];                                   // coalesced LDG
        float4 ra = *reinterpret_cast<const float4*>(&rowsT[d * RT]);     // broadcast
        float4 rb = *reinterpret_cast<const float4*>(&rowsT[d * RT + 4]); // broadcast
        acc[0] = fmaf(ra.x, w, acc[0]);
        acc[1] = fmaf(ra.y, w, acc[1]);
        acc[2] = fmaf(ra.z, w, acc[2]);
        acc[3] = fmaf(ra.w, w, acc[3]);
        acc[4] = fmaf(rb.x, w, acc[4]);
        acc[5] = fmaf(rb.y, w, acc[5]);
        acc[6] = fmaf(rb.z, w, acc[6]);
        acc[7] = fmaf(rb.w, w, acc[7]);
    }

    #pragma unroll
    for (int r = 0; r < RT; ++r)
        out[(size_t)(r0 + r) * H_ + t] = acc[r];
}

// ---------------------------------------------------------------------------
// Kernel B: KT k-rows per block. 256 threads.
// Phase 1: thread q computes KT scores (MUFU.TANH).
// Phase 2: KT masked softmaxes (q-axis mask).
// Phase 3: thread d accumulates KT outputs over q; value LDG reused KT times.
// ---------------------------------------------------------------------------
__global__ __launch_bounds__(256)
void attn_kernel(const float* __restrict__ value,
                 const int*   __restrict__ valid_lens,
                 const float* __restrict__ wv,
                 float*       __restrict__ out) {
    const int bk0 = blockIdx.x * KT;     // first k-row
    const int b   = bk0 >> 8;            // NK = 256
    const int t   = threadIdx.x;         // 0..255
    const int lane = t & 31;
    const int wid  = t >> 5;

    __shared__ float kvs[KT * H_];       // 4KB
    __shared__ float wvs[H_];
    __shared__ float attnT[NQ_ * KT];    // 8KB, attnT[q*KT + k]
    __shared__ float redm[KT][8];
    __shared__ float gred[KT];

    // stage KT kproj rows (contiguous) + wv
    {
        const float* src = g_kproj + (size_t)bk0 * H_;   // KT*128 = 1024 floats
        *reinterpret_cast<float4*>(&kvs[t * 4]) =
            *reinterpret_cast<const float4*>(src + t * 4);
        if (t < H_) wvs[t] = wv[t];
    }
    __syncthreads();

    // ---- Phase 1: scores for q = t, all KT k ----
    const float* qrow = g_qproj + (size_t)(b * NQ_ + t) * H_;
    float s[KT];
    #pragma unroll
    for (int k = 0; k < KT; ++k) s[k] = 0.f;

    #pragma unroll 2
    for (int h = 0; h < H_; h += 4) {
        float4 qv  = *reinterpret_cast<const float4*>(qrow + h);
        float4 wv4 = *reinterpret_cast<const float4*>(&wvs[h]);   // broadcast
        #pragma unroll
        for (int k = 0; k < KT; ++k) {
            float4 kv = *reinterpret_cast<const float4*>(&kvs[k * H_ + h]); // broadcast
            s[k] = fmaf(wv4.x, tanh_fast(kv.x + qv.x), s[k]);
            s[k] = fmaf(wv4.y, tanh_fast(kv.y + qv.y), s[k]);
            s[k] = fmaf(wv4.z, tanh_fast(kv.z + qv.z), s[k]);
            s[k] = fmaf(wv4.w, tanh_fast(kv.w + qv.w), s[k]);
        }
    }
    if (t >= valid_lens[b]) {
        #pragma unroll
        for (int k = 0; k < KT; ++k) s[k] = -1000000.0f;
    }

    // ---- Phase 2: masked softmax per k over the 256 q ----
    // block max per k
    #pragma unroll
    for (int k = 0; k < KT; ++k) {
        float m = s[k];
        #pragma unroll
        for (int o = 16; o > 0; o >>= 1)
            m = fmaxf(m, __shfl_xor_sync(0xffffffffu, m, o));
        if (lane == 0) redm[k][wid] = m;
    }
    __syncthreads();
    if (t < 64) {                        // warps 0,1 fully active
        int k = t >> 3, w = t & 7;
        float v = redm[k][w];
        v = fmaxf(v, __shfl_xor_sync(0xffffffffu, v, 4));
        v = fmaxf(v, __shfl_xor_sync(0xffffffffu, v, 2));
        v = fmaxf(v, __shfl_xor_sync(0xffffffffu, v, 1));
        if (w == 0) gred[k] = v;
    }
    __syncthreads();

    float e[KT];
    #pragma unroll
    for (int k = 0; k < KT; ++k)
        e[k] = __expf(s[k] - gred[k]);

    __syncthreads();   // gred reuse hazard
    // block sum per k
    #pragma unroll
    for (int k = 0; k < KT; ++k) {
        float sm = e[k];
        #pragma unroll
        for (int o = 16; o > 0; o >>= 1)
            sm += __shfl_xor_sync(0xffffffffu, sm, o);
        if (lane == 0) redm[k][wid] = sm;
    }
    __syncthreads();
    if (t < 64) {
        int k = t >> 3, w = t & 7;
        float v = redm[k][w];
        v += __shfl_xor_sync(0xffffffffu, v, 4);
        v += __shfl_xor_sync(0xffffffffu, v, 2);
        v += __shfl_xor_sync(0xffffffffu, v, 1);
        if (w == 0) gred[k] = v;
    }
    __syncthreads();

    // normalized attn, stored transposed: attnT[q*KT + k]
    {
        float a[KT];
        #pragma unroll
        for (int k = 0; k < KT; ++k)
            a[k] = e[k] * __frcp_rn(gred[k]);
        *reinterpret_cast<float4*>(&attnT[t * KT + 0]) = make_float4(a[0], a[1], a[2], a[3]);
        *reinterpret_cast<float4*>(&attnT[t * KT + 4]) = make_float4(a[4], a[5], a[6], a[7]);
    }
    __syncthreads();

    // ---- Phase 3: out[b, bk0+k, d], d = t ----
    const float* vcol = value + (size_t)b * NQ_ * DV_ + t;
    float acc[KT];
    #pragma unroll
    for (int k = 0; k < KT; ++k) acc[k] = 0.f;

    #pragma unroll 2
    for (int q = 0; q < NQ_; ++q) {
        float v = vcol[(size_t)q * DV_];                                   // coalesced LDG
        float4 a0 = *reinterpret_cast<const float4*>(&attnT[q * KT + 0]);  // broadcast
        float4 a1 = *reinterpret_cast<const float4*>(&attnT[q * KT + 4]);  // broadcast
        acc[0] = fmaf(a0.x, v, acc[0]);
        acc[1] = fmaf(a0.y, v, acc[1]);
        acc[2] = fmaf(a0.z, v, acc[2]);
        acc[3] = fmaf(a0.w, v, acc[3]);
        acc[4] = fmaf(a1.x, v, acc[4]);
        acc[5] = fmaf(a1.y, v, acc[5]);
        acc[6] = fmaf(a1.z, v, acc[6]);
        acc[7] = fmaf(a1.w, v, acc[7]);
    }
    #pragma unroll
    for (int k = 0; k < KT; ++k)
        out[(size_t)(bk0 + k) * DV_ + t] = acc[k];
}

// ---------------------------------------------------------------------------
extern "C" void kernel_launch(void* const* d_in, const int* in_sizes, int n_in,
                              void* d_out, int out_size) {
    const float* key        = (const float*)d_in[0];
    const float* query      = (const float*)d_in[1];
    const float* value      = (const float*)d_in[2];
    const int*   valid_lens = (const int*)  d_in[3];
    const float* Wk         = (const float*)d_in[4];
    const float* Wq         = (const float*)d_in[5];
    const float* wv         = (const float*)d_in[6];
    float* out = (float*)d_out;

    dim3 gridA(B_ * NK_ / RT, 2);
    proj_kernel<<<gridA, 128>>>(key, query, Wk, Wq);
    attn_kernel<<<B_ * NK_ / KT, 256>>>(value, valid_lens, wv, out);
}

// round 3
// speedup vs baseline: 3.9216x; 1.5941x over previous
#include <cuda_runtime.h>

#define B_  16
#define NK_ 256
#define NQ_ 256
#define DK_ 256
#define H_  128
#define DV_ 256
#define KT  4     // k-rows per attn block
#define RT  8     // rows per proj block

// scratch for projections (allocation-free rule: device globals)
__device__ float g_kproj[B_ * NK_ * H_];   // (B, NK, H)
__device__ float g_qproj[B_ * NQ_ * H_];   // (B, NQ, H)

__device__ __forceinline__ float tanh_fast(float x) {
    float y;
    asm("tanh.approx.f32 %0, %1;" : "=f"(y) : "f"(x));
    return y;
}

// ---------------------------------------------------------------------------
// Kernel A: projections, RT rows per block. blockIdx.y==0 -> key@Wk, 1 -> q@Wq.
// ---------------------------------------------------------------------------
__global__ __launch_bounds__(128)
void proj_kernel(const float* __restrict__ key,
                 const float* __restrict__ query,
                 const float* __restrict__ Wk,
                 const float* __restrict__ Wq) {
    __shared__ float rowsT[DK_ * RT];      // rowsT[d*RT + r]
    const float* in = blockIdx.y ? query : key;
    const float* W  = blockIdx.y ? Wq    : Wk;
    float* out      = blockIdx.y ? g_qproj : g_kproj;

    const int r0 = blockIdx.x * RT;
    const int t  = threadIdx.x;            // 0..127

    {
        const float* src = in + (size_t)r0 * DK_;
        int r = t >> 4;
        int d0 = (t & 15) * 16;
        #pragma unroll
        for (int i = 0; i < 4; ++i) {
            float4 v = *reinterpret_cast<const float4*>(src + r * DK_ + d0 + i * 4);
            rowsT[(d0 + i * 4 + 0) * RT + r] = v.x;
            rowsT[(d0 + i * 4 + 1) * RT + r] = v.y;
            rowsT[(d0 + i * 4 + 2) * RT + r] = v.z;
            rowsT[(d0 + i * 4 + 3) * RT + r] = v.w;
        }
    }
    __syncthreads();

    float acc[RT];
    #pragma unroll
    for (int r = 0; r < RT; ++r) acc[r] = 0.f;

    #pragma unroll 4
    for (int d = 0; d < DK_; ++d) {
        float w = W[d * H_ + t];
        float4 ra = *reinterpret_cast<const float4*>(&rowsT[d * RT]);
        float4 rb = *reinterpret_cast<const float4*>(&rowsT[d * RT + 4]);
        acc[0] = fmaf(ra.x, w, acc[0]);
        acc[1] = fmaf(ra.y, w, acc[1]);
        acc[2] = fmaf(ra.z, w, acc[2]);
        acc[3] = fmaf(ra.w, w, acc[3]);
        acc[4] = fmaf(rb.x, w, acc[4]);
        acc[5] = fmaf(rb.y, w, acc[5]);
        acc[6] = fmaf(rb.z, w, acc[6]);
        acc[7] = fmaf(rb.w, w, acc[7]);
    }

    #pragma unroll
    for (int r = 0; r < RT; ++r)
        out[(size_t)(r0 + r) * H_ + t] = acc[r];
}

// ---------------------------------------------------------------------------
// Kernel B: KT=4 k-rows per block, 256 threads, valid_lens early-skip.
// ---------------------------------------------------------------------------
__global__ __launch_bounds__(256)
void attn_kernel(const float* __restrict__ value,
                 const int*   __restrict__ valid_lens,
                 const float* __restrict__ wv,
                 float*       __restrict__ out) {
    const int bk0 = blockIdx.x * KT;
    const int b   = bk0 >> 8;            // NK = 256
    const int t   = threadIdx.x;         // 0..255
    const int lane = t & 31;
    const int wid  = t >> 5;

    __shared__ float kvs[KT * H_];       // 2KB
    __shared__ float wvs[H_];
    __shared__ float attnT[NQ_ * KT];    // 4KB, attnT[q*KT + k]
    __shared__ float redm[KT][8];
    __shared__ float gred[KT];

    const int vl = valid_lens[b];

    // stage KT kproj rows + wv
    {
        const float* src = g_kproj + (size_t)bk0 * H_;   // 512 floats
        *reinterpret_cast<float2*>(&kvs[t * 2]) =
            *reinterpret_cast<const float2*>(src + t * 2);
        if (t < H_) wvs[t] = wv[t];
    }
    __syncthreads();

    // ---- Phase 1: scores for q = t, all KT k (skip masked q entirely) ----
    float s[KT];
    if (t < vl) {
        const float* qrow = g_qproj + (size_t)(b * NQ_ + t) * H_;
        #pragma unroll
        for (int k = 0; k < KT; ++k) s[k] = 0.f;

        #pragma unroll 2
        for (int h = 0; h < H_; h += 4) {
            float4 qv  = *reinterpret_cast<const float4*>(qrow + h);
            float4 wv4 = *reinterpret_cast<const float4*>(&wvs[h]);
            #pragma unroll
            for (int k = 0; k < KT; ++k) {
                float4 kv = *reinterpret_cast<const float4*>(&kvs[k * H_ + h]);
                s[k] = fmaf(wv4.x, tanh_fast(kv.x + qv.x), s[k]);
                s[k] = fmaf(wv4.y, tanh_fast(kv.y + qv.y), s[k]);
                s[k] = fmaf(wv4.z, tanh_fast(kv.z + qv.z), s[k]);
                s[k] = fmaf(wv4.w, tanh_fast(kv.w + qv.w), s[k]);
            }
        }
    } else {
        #pragma unroll
        for (int k = 0; k < KT; ++k) s[k] = -1000000.0f;
    }

    // ---- Phase 2: masked softmax per k over 256 q ----
    #pragma unroll
    for (int k = 0; k < KT; ++k) {
        float m = s[k];
        #pragma unroll
        for (int o = 16; o > 0; o >>= 1)
            m = fmaxf(m, __shfl_xor_sync(0xffffffffu, m, o));
        if (lane == 0) redm[k][wid] = m;
    }
    __syncthreads();
    if (t < 32) {                        // one warp: k = t>>3 (0..3)
        int k = t >> 3, w = t & 7;
        float v = redm[k][w];
        v = fmaxf(v, __shfl_xor_sync(0xffffffffu, v, 4));
        v = fmaxf(v, __shfl_xor_sync(0xffffffffu, v, 2));
        v = fmaxf(v, __shfl_xor_sync(0xffffffffu, v, 1));
        if (w == 0) gred[k] = v;
    }
    __syncthreads();

    float e[KT];
    #pragma unroll
    for (int k = 0; k < KT; ++k)
        e[k] = __expf(s[k] - gred[k]);   // masked -> 0

    #pragma unroll
    for (int k = 0; k < KT; ++k) {
        float sm = e[k];
        #pragma unroll
        for (int o = 16; o > 0; o >>= 1)
            sm += __shfl_xor_sync(0xffffffffu, sm, o);
        if (lane == 0) redm[k][wid] = sm;
    }
    __syncthreads();
    if (t < 32) {
        int k = t >> 3, w = t & 7;
        float v = redm[k][w];
        v += __shfl_xor_sync(0xffffffffu, v, 4);
        v += __shfl_xor_sync(0xffffffffu, v, 2);
        v += __shfl_xor_sync(0xffffffffu, v, 1);
        if (w == 0) gred[k] = v;
    }
    __syncthreads();

    {
        float4 a;
        a.x = e[0] * __frcp_rn(gred[0]);
        a.y = e[1] * __frcp_rn(gred[1]);
        a.z = e[2] * __frcp_rn(gred[2]);
        a.w = e[3] * __frcp_rn(gred[3]);
        *reinterpret_cast<float4*>(&attnT[t * KT]) = a;
    }
    __syncthreads();

    // ---- Phase 3: out[b, bk0+k, d], d = t; only q < vl contribute ----
    const float* vcol = value + (size_t)b * NQ_ * DV_ + t;
    float a0 = 0.f, a1 = 0.f, a2 = 0.f, a3 = 0.f;

    int q = 0;
    const int vl4 = vl & ~3;
    for (; q < vl4; q += 4) {
        #pragma unroll
        for (int j = 0; j < 4; ++j) {
            float v = vcol[(size_t)(q + j) * DV_];
            float4 a = *reinterpret_cast<const float4*>(&attnT[(q + j) * KT]);
            a0 = fmaf(a.x, v, a0);
            a1 = fmaf(a.y, v, a1);
            a2 = fmaf(a.z, v, a2);
            a3 = fmaf(a.w, v, a3);
        }
    }
    for (; q < vl; ++q) {
        float v = vcol[(size_t)q * DV_];
        float4 a = *reinterpret_cast<const float4*>(&attnT[q * KT]);
        a0 = fmaf(a.x, v, a0);
        a1 = fmaf(a.y, v, a1);
        a2 = fmaf(a.z, v, a2);
        a3 = fmaf(a.w, v, a3);
    }

    out[(size_t)(bk0 + 0) * DV_ + t] = a0;
    out[(size_t)(bk0 + 1) * DV_ + t] = a1;
    out[(size_t)(bk0 + 2) * DV_ + t] = a2;
    out[(size_t)(bk0 + 3) * DV_ + t] = a3;
}

// ---------------------------------------------------------------------------
extern "C" void kernel_launch(void* const* d_in, const int* in_sizes, int n_in,
                              void* d_out, int out_size) {
    const float* key        = (const float*)d_in[0];
    const float* query      = (const float*)d_in[1];
    const float* value      = (const float*)d_in[2];
    const int*   valid_lens = (const int*)  d_in[3];
    const float* Wk         = (const float*)d_in[4];
    const float* Wq         = (const float*)d_in[5];
    const float* wv         = (const float*)d_in[6];
    float* out = (float*)d_out;

    dim3 gridA(B_ * NK_ / RT, 2);
    proj_kernel<<<gridA, 128>>>(key, query, Wk, Wq);
    attn_kernel<<<B_ * NK_ / KT, 256>>>(value, valid_lens, wv, out);
}